// round 5
// baseline (speedup 1.0000x reference)
#include <cuda_runtime.h>

#define PDIM 128
#define HEADS 4
#define EDIM 32
#define NSEG 32
#define CAP 256
#define NMAX 4096
#define QST_PITCH 260
#define KPITCH 36
#define NK_MAX (CAP / 32)

typedef unsigned long long u64;

// Packed fp32x2 ops (sm_100+; ptxas never emits FFMA2 from C++ — PTX only)
#define FMA2(d, a, b, c) \
    asm("fma.rn.f32x2 %0, %1, %2, %3;" : "=l"(d) : "l"(a), "l"(b), "l"(c))
#define ADD2(d, a, b) \
    asm("add.rn.f32x2 %0, %1, %2;" : "=l"(d) : "l"(a), "l"(b))
#define PACK2(d, lo, hi) \
    asm("mov.b64 %0, {%1, %2};" : "=l"(d) : "r"(__float_as_uint(lo)), "r"(__float_as_uint(hi)))
#define UNPK2(lo, hi, s) do { unsigned _a, _b; \
    asm("mov.b64 {%0, %1}, %2;" : "=r"(_a), "=r"(_b) : "l"(s)); \
    lo = __uint_as_float(_a); hi = __uint_as_float(_b); } while (0)

// Scratch (allocation-free rule: device globals)
__device__ float g_Q[NMAX * PDIM];
__device__ float g_K[NMAX * PDIM];
__device__ float g_V[NMAX * PDIM];
__device__ int   g_rowlist[NMAX];
__device__ int   g_segstart[NSEG + 1];

#define QKV_SMEM_BYTES (128 * 128 * 4)      // full W tile (build path fits inside)
// attn: Ks[256][36] + Vs[256][32] + QsT[32][260] + wb[32][32][4] + rows[256]
#define ATTN_SMEM_BYTES ((CAP*KPITCH + CAP*32 + 32*QST_PITCH + 32*32*4) * 4 + CAP * 4)

// ---------------------------------------------------------------------------
// Kernel 1 (fused): QKV projection + segment build.
// grid (n/32, 4), block 256.
//  y<3: GEMM for W_{q,k,v}. Tile 32 rows x 128 cols, 4x4 per thread, f32x2.
//  y==3, x==0: deterministic stable counting sort of rows by segment.
// ---------------------------------------------------------------------------
__global__ __launch_bounds__(256, 3)
void qkv_build(const float* __restrict__ inp,
               const float* __restrict__ Wq, const float* __restrict__ bq,
               const float* __restrict__ Wk, const float* __restrict__ bk,
               const float* __restrict__ Wv, const float* __restrict__ bv,
               const int* __restrict__ pos, int n)
{
    extern __shared__ float sm[];
    const int y = blockIdx.y;
    const int tid = threadIdx.x;

    if (y == 3) {
        // ---------------- build_seg path ----------------
        if (blockIdx.x != 0) return;
        int* cnt  = (int*)sm;            // [NSEG*256]
        int* tsum = cnt + NSEG * 256;    // [256]

        const int t = tid;
        const int chunk = (n + 255) / 256;
        const int lo = t * chunk;
        const int hi = min(n, lo + chunk);

#pragma unroll
        for (int s = 0; s < NSEG; s++) cnt[s * 256 + t] = 0;
        __syncthreads();
        for (int i = lo; i < hi; i++) cnt[pos[i] * 256 + t]++;
        __syncthreads();
        {
            int sum = 0;
#pragma unroll
            for (int j = 0; j < 32; j++) {
                int v = cnt[t * 32 + j];
                cnt[t * 32 + j] = sum;
                sum += v;
            }
            tsum[t] = sum;
        }
        __syncthreads();
        if (t == 0) {
            int a = 0;
            for (int i = 0; i < 256; i++) { int v = tsum[i]; tsum[i] = a; a += v; }
        }
        __syncthreads();
        {
            int b = tsum[t];
#pragma unroll
            for (int j = 0; j < 32; j++) cnt[t * 32 + j] += b;
        }
        __syncthreads();
        if (t < NSEG) g_segstart[t] = cnt[t * 256 + 0];
        if (t == 0) g_segstart[NSEG] = n;
        for (int i = lo; i < hi; i++) {
            int s = pos[i];
            int idx = cnt[s * 256 + t]++;
            g_rowlist[idx] = i;
        }
        return;
    }

    // ---------------- GEMM path ----------------
    const int which = y;
    const float* W    = (which == 0) ? Wq : (which == 1) ? Wk : Wv;
    const float* bias = (which == 0) ? bq : (which == 1) ? bk : bv;
    float* Out        = (which == 0) ? g_Q : (which == 1) ? g_K : g_V;

    // Stage full W (128x128) as float4, coalesced
    float4* Bs4 = (float4*)sm;
    const float4* W4 = (const float4*)W;
    for (int i = tid; i < 128 * 32; i += 256) Bs4[i] = W4[i];
    __syncthreads();

    const ulonglong2* Bs2 = (const ulonglong2*)sm;   // same layout, paired view

    const int base = blockIdx.x * 32;
    const int tx = tid & 31;          // col group: cols tx*4..+3
    const int ty = tid >> 5;          // row group: rows base+ty*4..+3
    const int r0 = base + ty * 4;

    const float4* A4 = (const float4*)inp;
    int r[4];
#pragma unroll
    for (int i = 0; i < 4; i++) r[i] = min(r0 + i, n - 1);

    u64 acc[4][2];
#pragma unroll
    for (int i = 0; i < 4; i++) { acc[i][0] = 0ull; acc[i][1] = 0ull; }

#pragma unroll 4
    for (int kc = 0; kc < 32; kc++) {            // k in chunks of 4
        float4 a[4];
#pragma unroll
        for (int i = 0; i < 4; i++) a[i] = A4[(size_t)r[i] * 32 + kc];
#pragma unroll
        for (int kk = 0; kk < 4; kk++) {
            ulonglong2 b2 = Bs2[(kc * 4 + kk) * 32 + tx];   // {b0,b1},{b2,b3}
#pragma unroll
            for (int i = 0; i < 4; i++) {
                float av = ((const float*)&a[i])[kk];
                u64 aa; PACK2(aa, av, av);
                FMA2(acc[i][0], aa, b2.x, acc[i][0]);
                FMA2(acc[i][1], aa, b2.y, acc[i][1]);
            }
        }
    }

    float4 bi = ((const float4*)bias)[tx];
    u64 b01, b23;
    PACK2(b01, bi.x, bi.y);
    PACK2(b23, bi.z, bi.w);
#pragma unroll
    for (int i = 0; i < 4; i++) {
        int row = r0 + i;
        if (row < n) {
            u64 o0, o1;
            ADD2(o0, acc[i][0], b01);
            ADD2(o1, acc[i][1], b23);
            ulonglong2 st; st.x = o0; st.y = o1;
            ((ulonglong2*)Out)[(size_t)row * 32 + tx] = st;
        }
    }
}

// ---------------------------------------------------------------------------
// Kernel 2: fast-path attention. grid (NSEG, HEADS), block 1024 (32 warps).
// 4 queries per warp; f32x2 accumulation for scores and PV.
// ---------------------------------------------------------------------------
__global__ __launch_bounds__(1024)
void seg_attn(float* __restrict__ out)
{
    extern __shared__ float sm[];
    float* Ks  = sm;                          // [CAP][KPITCH]
    float* Vs  = Ks + CAP * KPITCH;           // [CAP][32]
    float* QsT = Vs + CAP * 32;               // [32][QST_PITCH] (pre-scaled)
    float* wb  = QsT + 32 * QST_PITCH;        // [32 warps][32][4]
    int*  rows = (int*)(wb + 32 * 32 * 4);    // [CAP]

    const int s = blockIdx.x, h = blockIdx.y;
    const int start = g_segstart[s];
    const int len = g_segstart[s + 1] - start;
    if (len == 0 || len > CAP) return;

    const int tid = threadIdx.x, lane = tid & 31, warp = tid >> 5;
    const int hoff = h * EDIM;
    const float scale = 0.17677669529663687f;   // 1/sqrt(32)

    const int nk = (len + 31) >> 5;
    const int lenp = nk * 32;

    if (tid < len) rows[tid] = g_rowlist[start + tid];
    // Stage K, V (zero-padded to lenp), Q transposed & pre-scaled.
    for (int i = tid; i < lenp * 8; i += 1024) {
        int j = i >> 3, e4 = i & 7;
        float4 kv = make_float4(0.f, 0.f, 0.f, 0.f);
        float4 vv = kv, qv = kv;
        if (j < len) {
            int row = g_rowlist[start + j];
            kv = *(const float4*)&g_K[(size_t)row * PDIM + hoff + e4 * 4];
            vv = *(const float4*)&g_V[(size_t)row * PDIM + hoff + e4 * 4];
            qv = *(const float4*)&g_Q[(size_t)row * PDIM + hoff + e4 * 4];
        }
        *(float4*)&Ks[j * KPITCH + e4 * 4] = kv;
        *(float4*)&Vs[j * 32 + e4 * 4] = vv;
        QsT[(e4 * 4 + 0) * QST_PITCH + j] = qv.x * scale;
        QsT[(e4 * 4 + 1) * QST_PITCH + j] = qv.y * scale;
        QsT[(e4 * 4 + 2) * QST_PITCH + j] = qv.z * scale;
        QsT[(e4 * 4 + 3) * QST_PITCH + j] = qv.w * scale;
    }
    __syncthreads();

    float* wbW = wb + warp * 128;

    for (int qb = warp * 4; qb < len; qb += 128) {
        // ---- scores: lane = key within chunk, query pairs packed ----
        float sc[4][NK_MAX];
#pragma unroll
        for (int kk = 0; kk < NK_MAX; kk++) {
            if (kk < nk) {
                int j = kk * 32 + lane;
                u64 s01 = 0ull, s23 = 0ull;
                const float* kp = &Ks[j * KPITCH];
                // two halves of 16 e's to bound register pressure
#pragma unroll
                for (int half = 0; half < 2; half++) {
                    float4 kr[4];
#pragma unroll
                    for (int c = 0; c < 4; c++)
                        kr[c] = *(const float4*)&kp[half * 16 + c * 4];
#pragma unroll
                    for (int ee = 0; ee < 16; ee++) {
                        int e = half * 16 + ee;
                        float ke = ((const float*)kr)[ee];
                        u64 kk2; PACK2(kk2, ke, ke);
                        ulonglong2 q2 = *(const ulonglong2*)&QsT[e * QST_PITCH + qb];
                        FMA2(s01, kk2, q2.x, s01);
                        FMA2(s23, kk2, q2.y, s23);
                    }
                }
                float a0, a1, a2, a3;
                UNPK2(a0, a1, s01);
                UNPK2(a2, a3, s23);
                bool valid = (j < len);
                sc[0][kk] = valid ? a0 : -1e30f;
                sc[1][kk] = valid ? a1 : -1e30f;
                sc[2][kk] = valid ? a2 : -1e30f;
                sc[3][kk] = valid ? a3 : -1e30f;
            }
        }
        // ---- softmax per query ----
        float inv[4];
#pragma unroll
        for (int qi = 0; qi < 4; qi++) {
            float m = -1e30f;
#pragma unroll
            for (int kk = 0; kk < NK_MAX; kk++)
                if (kk < nk) m = fmaxf(m, sc[qi][kk]);
#pragma unroll
            for (int o = 16; o > 0; o >>= 1)
                m = fmaxf(m, __shfl_xor_sync(0xffffffffu, m, o));
            float l = 0.f;
#pragma unroll
            for (int kk = 0; kk < NK_MAX; kk++) {
                if (kk < nk) {
                    float e = __expf(sc[qi][kk] - m);
                    sc[qi][kk] = e;
                    l += e;
                }
            }
#pragma unroll
            for (int o = 16; o > 0; o >>= 1)
                l += __shfl_xor_sync(0xffffffffu, l, o);
            inv[qi] = 1.f / l;
        }
        // ---- PV in 32-key chunks through per-warp staging, packed ----
        u64 a01 = 0ull, a23 = 0ull;
#pragma unroll
        for (int kk = 0; kk < NK_MAX; kk++) {
            if (kk < nk) {
                float4 w4;
                w4.x = sc[0][kk] * inv[0];
                w4.y = sc[1][kk] * inv[1];
                w4.z = sc[2][kk] * inv[2];
                w4.w = sc[3][kk] * inv[3];
                *(float4*)&wbW[lane * 4] = w4;
                __syncwarp();
                const float* vbase = &Vs[kk * 32 * 32 + lane];
#pragma unroll
                for (int src = 0; src < 32; src++) {
                    float v = vbase[src * 32];
                    u64 vv; PACK2(vv, v, v);
                    ulonglong2 w2 = *(const ulonglong2*)&wbW[src * 4];
                    FMA2(a01, vv, w2.x, a01);
                    FMA2(a23, vv, w2.y, a23);
                }
                __syncwarp();
            }
        }
        float o0, o1, o2, o3;
        UNPK2(o0, o1, a01);
        UNPK2(o2, o3, a23);

        if (qb + 0 < len) out[(size_t)rows[qb + 0] * PDIM + hoff + lane] = o0;
        if (qb + 1 < len) out[(size_t)rows[qb + 1] * PDIM + hoff + lane] = o1;
        if (qb + 2 < len) out[(size_t)rows[qb + 2] * PDIM + hoff + lane] = o2;
        if (qb + 3 < len) out[(size_t)rows[qb + 3] * PDIM + hoff + lane] = o3;
    }
}

// ---------------------------------------------------------------------------
// Kernel 3: slow-path attention for len > CAP (statistically never; early-exit).
// ---------------------------------------------------------------------------
__global__ __launch_bounds__(512)
void seg_attn_slow(float* __restrict__ out)
{
    const int s = blockIdx.x, h = blockIdx.y;
    const int start = g_segstart[s];
    const int len = g_segstart[s + 1] - start;
    if (len <= CAP) return;

    __shared__ float qbuf[16][32];
    const int tid = threadIdx.x, lane = tid & 31, warp = tid >> 5;
    const int hoff = h * EDIM;
    const float scale = 0.17677669529663687f;

    for (int q = warp; q < len; q += 16) {
        const int row = g_rowlist[start + q];
        qbuf[warp][lane] = g_Q[(size_t)row * PDIM + hoff + lane];
        __syncwarp();
        float qv[32];
#pragma unroll
        for (int e = 0; e < 32; e++) qv[e] = qbuf[warp][e];

        float m = -1e30f;
        for (int j = lane; j < len; j += 32) {
            const float* kp = &g_K[(size_t)g_rowlist[start + j] * PDIM + hoff];
            float sdot = 0.f;
#pragma unroll
            for (int e = 0; e < 32; e++) sdot = fmaf(qv[e], kp[e], sdot);
            m = fmaxf(m, sdot * scale);
        }
#pragma unroll
        for (int o = 16; o > 0; o >>= 1) m = fmaxf(m, __shfl_xor_sync(0xffffffffu, m, o));

        float l = 0.f;
        float accv[32];
#pragma unroll
        for (int e = 0; e < 32; e++) accv[e] = 0.f;
        for (int j = lane; j < len; j += 32) {
            int r2 = g_rowlist[start + j];
            const float* kp = &g_K[(size_t)r2 * PDIM + hoff];
            float sdot = 0.f;
#pragma unroll
            for (int e = 0; e < 32; e++) sdot = fmaf(qv[e], kp[e], sdot);
            float w = __expf(sdot * scale - m);
            l += w;
            const float* vp = &g_V[(size_t)r2 * PDIM + hoff];
#pragma unroll
            for (int e = 0; e < 32; e++) accv[e] = fmaf(w, vp[e], accv[e]);
        }
#pragma unroll
        for (int o = 16; o > 0; o >>= 1) l += __shfl_xor_sync(0xffffffffu, l, o);
#pragma unroll
        for (int e = 0; e < 32; e++) {
            float r = accv[e];
#pragma unroll
            for (int o = 16; o > 0; o >>= 1) r += __shfl_xor_sync(0xffffffffu, r, o);
            if (lane == 0) qbuf[warp][e] = r;
        }
        __syncwarp();
        out[(size_t)row * PDIM + hoff + lane] = qbuf[warp][lane] / l;
        __syncwarp();
    }
}

// ---------------------------------------------------------------------------
extern "C" void kernel_launch(void* const* d_in, const int* in_sizes, int n_in,
                              void* d_out, int out_size)
{
    const float* inp = (const float*)d_in[0];
    const int*   pos = (const int*)d_in[1];
    const float* Wq  = (const float*)d_in[2];
    const float* bq  = (const float*)d_in[3];
    const float* Wk  = (const float*)d_in[4];
    const float* bk  = (const float*)d_in[5];
    const float* Wv  = (const float*)d_in[6];
    const float* bv  = (const float*)d_in[7];
    float* out = (float*)d_out;
    const int n = in_sizes[1];

    cudaFuncSetAttribute(qkv_build, cudaFuncAttributeMaxDynamicSharedMemorySize, QKV_SMEM_BYTES);
    cudaFuncSetAttribute(seg_attn, cudaFuncAttributeMaxDynamicSharedMemorySize, ATTN_SMEM_BYTES);

    const int row_blocks = (n + 31) / 32;
    qkv_build<<<dim3(row_blocks, 4), 256, QKV_SMEM_BYTES>>>(inp, Wq, bq, Wk, bk, Wv, bv, pos, n);
    seg_attn<<<dim3(NSEG, HEADS), 1024, ATTN_SMEM_BYTES>>>(out);
    seg_attn_slow<<<dim3(NSEG, HEADS), 512>>>(out);
}

// round 8
// speedup vs baseline: 1.6796x; 1.6796x over previous
#include <cuda_runtime.h>
#include <cstdint>

#define PDIM 128
#define HEADS 4
#define EDIM 32
#define NSEG 32
#define CAP 256
#define NMAX 4096
#define QST_PITCH 260
#define NK_MAX (CAP / 32)

// Scratch (allocation-free rule: device globals)
__device__ float g_Q[NMAX * PDIM];
__device__ float g_K[NMAX * PDIM];
__device__ float g_V[NMAX * PDIM];
__device__ int   g_rowlist[NMAX];
__device__ int   g_segstart[NSEG + 1];

// ---- GEMM smem layout (u32 units). bf16-pair words [row][kpair], pitch 68.
#define SPITCH 68
#define AS_H 0
#define AS_L (AS_H + 64 * SPITCH)
#define BS_H (AS_L + 64 * SPITCH)
#define BS_L (BS_H + 128 * SPITCH)
#define QKV_SMEM_U32 (BS_L + 128 * SPITCH)
#define QKV_SMEM_BYTES (QKV_SMEM_U32 * 4)

// attn smem: Ks[256][33] + Vs[256][32] + QsT[32][260] + wb[32][32][4] + rows[256]
#define ATTN_SMEM_BYTES ((CAP*33 + CAP*32 + 32*QST_PITCH + 32*32*4) * 4 + CAP * 4)

// bf16 m16n8k16 MMA, fp32 accumulate (sm_80+ PTX; HMMA pipe; no 'a' target needed)
#define MMA_BF16(d, a0, a1, a2, a3, b0, b1) \
    asm volatile("mma.sync.aligned.m16n8k16.row.col.f32.bf16.bf16.f32 " \
        "{%0,%1,%2,%3}, {%4,%5,%6,%7}, {%8,%9}, {%0,%1,%2,%3};" \
        : "+f"((d)[0]), "+f"((d)[1]), "+f"((d)[2]), "+f"((d)[3]) \
        : "r"(a0), "r"(a1), "r"(a2), "r"(a3), "r"(b0), "r"(b1))

// Split fp32 pair -> packed bf16x2 hi (truncation) and lo (exact residual, truncated)
__device__ __forceinline__ void split_pack(float x, float y, uint32_t& hi, uint32_t& lo) {
    uint32_t ux = __float_as_uint(x), uy = __float_as_uint(y);
    hi = __byte_perm(ux, uy, 0x7632);
    float hx = __uint_as_float(ux & 0xFFFF0000u);
    float hy = __uint_as_float(uy & 0xFFFF0000u);
    float lx = x - hx, ly = y - hy;
    lo = __byte_perm(__float_as_uint(lx), __float_as_uint(ly), 0x7632);
}

// ---------------------------------------------------------------------------
// Kernel 1 (fused): bf16-split tensor-core QKV projection + segment build.
// grid (n/64, 4), block 256.
//  y<3: 64x128x128 GEMM tile for W_{q,k,v} via mma.sync m16n8k16.
//  y==3, x==0: deterministic stable counting sort of rows by segment.
// ---------------------------------------------------------------------------
__global__ __launch_bounds__(256, 2)
void qkv_build(const float* __restrict__ inp,
               const float* __restrict__ Wq, const float* __restrict__ bq,
               const float* __restrict__ Wk, const float* __restrict__ bk,
               const float* __restrict__ Wv, const float* __restrict__ bv,
               const int* __restrict__ pos, int n)
{
    extern __shared__ float sm[];
    const int y = blockIdx.y;
    const int tid = threadIdx.x;

    if (y == 3) {
        // ---------------- build_seg path ----------------
        if (blockIdx.x != 0) return;
        int* cnt  = (int*)sm;            // [NSEG*256]
        int* tsum = cnt + NSEG * 256;    // [256]

        const int t = tid;
        const int chunk = (n + 255) / 256;
        const int lo = t * chunk;
        const int hi = min(n, lo + chunk);

#pragma unroll
        for (int s = 0; s < NSEG; s++) cnt[s * 256 + t] = 0;
        __syncthreads();
        for (int i = lo; i < hi; i++) cnt[pos[i] * 256 + t]++;
        __syncthreads();
        {
            int sum = 0;
#pragma unroll
            for (int j = 0; j < 32; j++) {
                int v = cnt[t * 32 + j];
                cnt[t * 32 + j] = sum;
                sum += v;
            }
            tsum[t] = sum;
        }
        __syncthreads();
        if (t == 0) {
            int a = 0;
            for (int i = 0; i < 256; i++) { int v = tsum[i]; tsum[i] = a; a += v; }
        }
        __syncthreads();
        {
            int b = tsum[t];
#pragma unroll
            for (int j = 0; j < 32; j++) cnt[t * 32 + j] += b;
        }
        __syncthreads();
        if (t < NSEG) g_segstart[t] = cnt[t * 256 + 0];
        if (t == 0) g_segstart[NSEG] = n;
        for (int i = lo; i < hi; i++) {
            int s = pos[i];
            int idx = cnt[s * 256 + t]++;
            g_rowlist[idx] = i;
        }
        return;
    }

    // ---------------- tensor GEMM path ----------------
    const int which = y;
    const float* W    = (which == 0) ? Wq : (which == 1) ? Wk : Wv;
    const float* bias = (which == 0) ? bq : (which == 1) ? bk : bv;
    float* Out        = (which == 0) ? g_Q : (which == 1) ? g_K : g_V;

    uint32_t* smu = (uint32_t*)sm;
    const int base = blockIdx.x * 64;

    // Stage A (64 rows x 64 kpairs): coalesced float2 LDG, conflict-free STS
    for (int i = tid; i < 64 * 64; i += 256) {
        int r = i >> 6, kp = i & 63;
        int row = min(base + r, n - 1);
        float2 a = *(const float2*)&inp[(size_t)row * PDIM + kp * 2];
        uint32_t h, l;
        split_pack(a.x, a.y, h, l);
        smu[AS_H + r * SPITCH + kp] = h;
        smu[AS_L + r * SPITCH + kp] = l;
    }
    // Stage B = W as [n][kpair] (value pair W[2kp][n], W[2kp+1][n]): coalesced LDG over n
    for (int i = tid; i < 128 * 64; i += 256) {
        int nn = i & 127, kp = i >> 7;
        float w0 = W[(2 * kp) * PDIM + nn];
        float w1 = W[(2 * kp + 1) * PDIM + nn];
        uint32_t h, l;
        split_pack(w0, w1, h, l);
        smu[BS_H + nn * SPITCH + kp] = h;
        smu[BS_L + nn * SPITCH + kp] = l;
    }
    __syncthreads();

    const int lane = tid & 31, wid = tid >> 5;
    const int wtm = wid >> 2, wtn = wid & 3;     // 2 warps in M, 4 in N
    const int l4 = lane >> 2, lq = lane & 3;

    float acc[2][4][4];
#pragma unroll
    for (int mt = 0; mt < 2; mt++)
#pragma unroll
        for (int nt = 0; nt < 4; nt++)
#pragma unroll
            for (int c = 0; c < 4; c++) acc[mt][nt][c] = 0.f;

#pragma unroll
    for (int ks = 0; ks < 8; ks++) {
        const int kb = ks * 8 + lq;
        uint32_t ah[2][4], al[2][4];
#pragma unroll
        for (int mt = 0; mt < 2; mt++) {
            int r = wtm * 32 + mt * 16 + l4;
            ah[mt][0] = smu[AS_H + r * SPITCH + kb];
            ah[mt][1] = smu[AS_H + (r + 8) * SPITCH + kb];
            ah[mt][2] = smu[AS_H + r * SPITCH + kb + 4];
            ah[mt][3] = smu[AS_H + (r + 8) * SPITCH + kb + 4];
            al[mt][0] = smu[AS_L + r * SPITCH + kb];
            al[mt][1] = smu[AS_L + (r + 8) * SPITCH + kb];
            al[mt][2] = smu[AS_L + r * SPITCH + kb + 4];
            al[mt][3] = smu[AS_L + (r + 8) * SPITCH + kb + 4];
        }
#pragma unroll
        for (int nt = 0; nt < 4; nt++) {
            int c = wtn * 32 + nt * 8 + l4;
            uint32_t bh0 = smu[BS_H + c * SPITCH + kb];
            uint32_t bh1 = smu[BS_H + c * SPITCH + kb + 4];
            uint32_t bl0 = smu[BS_L + c * SPITCH + kb];
            uint32_t bl1 = smu[BS_L + c * SPITCH + kb + 4];
#pragma unroll
            for (int mt = 0; mt < 2; mt++) {
                MMA_BF16(acc[mt][nt], ah[mt][0], ah[mt][1], ah[mt][2], ah[mt][3], bh0, bh1);
                MMA_BF16(acc[mt][nt], al[mt][0], al[mt][1], al[mt][2], al[mt][3], bh0, bh1);
                MMA_BF16(acc[mt][nt], ah[mt][0], ah[mt][1], ah[mt][2], ah[mt][3], bl0, bl1);
            }
        }
    }

    // Epilogue: fragment rows (l4, l4+8), cols lq*2, lq*2+1 -> float2 stores
#pragma unroll
    for (int nt = 0; nt < 4; nt++) {
        int col = wtn * 32 + nt * 8 + lq * 2;
        float2 bi = *(const float2*)&bias[col];
#pragma unroll
        for (int mt = 0; mt < 2; mt++) {
            int row0 = base + wtm * 32 + mt * 16 + l4;
            if (row0 < n) {
                float2 o; o.x = acc[mt][nt][0] + bi.x; o.y = acc[mt][nt][1] + bi.y;
                *(float2*)&Out[(size_t)row0 * PDIM + col] = o;
            }
            if (row0 + 8 < n) {
                float2 o; o.x = acc[mt][nt][2] + bi.x; o.y = acc[mt][nt][3] + bi.y;
                *(float2*)&Out[(size_t)(row0 + 8) * PDIM + col] = o;
            }
        }
    }
}

// ---------------------------------------------------------------------------
// Kernel 2: fast-path attention (R4 version, best measured). block 1024.
// ---------------------------------------------------------------------------
__global__ __launch_bounds__(1024)
void seg_attn(float* __restrict__ out)
{
    extern __shared__ float sm[];
    float* Ks  = sm;                          // [CAP][33]
    float* Vs  = Ks + CAP * 33;               // [CAP][32]
    float* QsT = Vs + CAP * 32;               // [32][QST_PITCH]
    float* wb  = QsT + 32 * QST_PITCH;        // [32 warps][32][4]
    int*  rows = (int*)(wb + 32 * 32 * 4);    // [CAP]

    const int s = blockIdx.x, h = blockIdx.y;
    const int start = g_segstart[s];
    const int len = g_segstart[s + 1] - start;
    if (len == 0 || len > CAP) return;

    const int tid = threadIdx.x, lane = tid & 31, warp = tid >> 5;
    const int hoff = h * EDIM;
    const float scale = 0.17677669529663687f;   // 1/sqrt(32)

    const int nk = (len + 31) >> 5;
    const int lenp = nk * 32;

    if (tid < len) rows[tid] = g_rowlist[start + tid];
    for (int i = tid; i < lenp * 8; i += 1024) {
        int j = i >> 3, e4 = i & 7;
        float4 kv = make_float4(0.f, 0.f, 0.f, 0.f);
        float4 vv = kv, qv = kv;
        if (j < len) {
            int row = g_rowlist[start + j];
            kv = *(const float4*)&g_K[(size_t)row * PDIM + hoff + e4 * 4];
            vv = *(const float4*)&g_V[(size_t)row * PDIM + hoff + e4 * 4];
            qv = *(const float4*)&g_Q[(size_t)row * PDIM + hoff + e4 * 4];
        }
        float* kd = &Ks[j * 33 + e4 * 4];
        kd[0] = kv.x; kd[1] = kv.y; kd[2] = kv.z; kd[3] = kv.w;
        *(float4*)&Vs[j * 32 + e4 * 4] = vv;
        QsT[(e4 * 4 + 0) * QST_PITCH + j] = qv.x;
        QsT[(e4 * 4 + 1) * QST_PITCH + j] = qv.y;
        QsT[(e4 * 4 + 2) * QST_PITCH + j] = qv.z;
        QsT[(e4 * 4 + 3) * QST_PITCH + j] = qv.w;
    }
    __syncthreads();

    float* wbW = wb + warp * 128;

    for (int qb = warp * 4; qb < len; qb += 128) {
        float sc[4][NK_MAX];
#pragma unroll
        for (int kk = 0; kk < NK_MAX; kk++) {
            if (kk < nk) {
                int j = kk * 32 + lane;
                float a0 = 0.f, a1 = 0.f, a2 = 0.f, a3 = 0.f;
                const float* kp = &Ks[j * 33];
#pragma unroll
                for (int e = 0; e < 32; e++) {
                    float ke = kp[e];
                    float4 q4 = *(const float4*)&QsT[e * QST_PITCH + qb];
                    a0 = fmaf(ke, q4.x, a0);
                    a1 = fmaf(ke, q4.y, a1);
                    a2 = fmaf(ke, q4.z, a2);
                    a3 = fmaf(ke, q4.w, a3);
                }
                bool valid = (j < len);
                sc[0][kk] = valid ? a0 * scale : -1e30f;
                sc[1][kk] = valid ? a1 * scale : -1e30f;
                sc[2][kk] = valid ? a2 * scale : -1e30f;
                sc[3][kk] = valid ? a3 * scale : -1e30f;
            }
        }
        float inv[4];
#pragma unroll
        for (int qi = 0; qi < 4; qi++) {
            float m = -1e30f;
#pragma unroll
            for (int kk = 0; kk < NK_MAX; kk++)
                if (kk < nk) m = fmaxf(m, sc[qi][kk]);
#pragma unroll
            for (int o = 16; o > 0; o >>= 1)
                m = fmaxf(m, __shfl_xor_sync(0xffffffffu, m, o));
            float l = 0.f;
#pragma unroll
            for (int kk = 0; kk < NK_MAX; kk++) {
                if (kk < nk) {
                    float e = __expf(sc[qi][kk] - m);
                    sc[qi][kk] = e;
                    l += e;
                }
            }
#pragma unroll
            for (int o = 16; o > 0; o >>= 1)
                l += __shfl_xor_sync(0xffffffffu, l, o);
            inv[qi] = 1.f / l;
        }
        float a0 = 0.f, a1 = 0.f, a2 = 0.f, a3 = 0.f;
#pragma unroll
        for (int kk = 0; kk < NK_MAX; kk++) {
            if (kk < nk) {
                float4 w4;
                w4.x = sc[0][kk] * inv[0];
                w4.y = sc[1][kk] * inv[1];
                w4.z = sc[2][kk] * inv[2];
                w4.w = sc[3][kk] * inv[3];
                *(float4*)&wbW[lane * 4] = w4;
                __syncwarp();
                const float* vbase = &Vs[kk * 32 * 32 + lane];
#pragma unroll
                for (int src = 0; src < 32; src++) {
                    float v = vbase[src * 32];
                    float4 w = *(const float4*)&wbW[src * 4];
                    a0 = fmaf(w.x, v, a0); a1 = fmaf(w.y, v, a1);
                    a2 = fmaf(w.z, v, a2); a3 = fmaf(w.w, v, a3);
                }
                __syncwarp();
            }
        }

        if (qb + 0 < len) out[(size_t)rows[qb + 0] * PDIM + hoff + lane] = a0;
        if (qb + 1 < len) out[(size_t)rows[qb + 1] * PDIM + hoff + lane] = a1;
        if (qb + 2 < len) out[(size_t)rows[qb + 2] * PDIM + hoff + lane] = a2;
        if (qb + 3 < len) out[(size_t)rows[qb + 3] * PDIM + hoff + lane] = a3;
    }
}

// ---------------------------------------------------------------------------
// Kernel 3: slow-path attention for len > CAP (statistically never; early-exit).
// ---------------------------------------------------------------------------
__global__ __launch_bounds__(512)
void seg_attn_slow(float* __restrict__ out)
{
    const int s = blockIdx.x, h = blockIdx.y;
    const int start = g_segstart[s];
    const int len = g_segstart[s + 1] - start;
    if (len <= CAP) return;

    __shared__ float qbuf[16][32];
    const int tid = threadIdx.x, lane = tid & 31, warp = tid >> 5;
    const int hoff = h * EDIM;
    const float scale = 0.17677669529663687f;

    for (int q = warp; q < len; q += 16) {
        const int row = g_rowlist[start + q];
        qbuf[warp][lane] = g_Q[(size_t)row * PDIM + hoff + lane];
        __syncwarp();
        float qv[32];
#pragma unroll
        for (int e = 0; e < 32; e++) qv[e] = qbuf[warp][e];

        float m = -1e30f;
        for (int j = lane; j < len; j += 32) {
            const float* kp = &g_K[(size_t)g_rowlist[start + j] * PDIM + hoff];
            float sdot = 0.f;
#pragma unroll
            for (int e = 0; e < 32; e++) sdot = fmaf(qv[e], kp[e], sdot);
            m = fmaxf(m, sdot * scale);
        }
#pragma unroll
        for (int o = 16; o > 0; o >>= 1) m = fmaxf(m, __shfl_xor_sync(0xffffffffu, m, o));

        float l = 0.f;
        float accv[32];
#pragma unroll
        for (int e = 0; e < 32; e++) accv[e] = 0.f;
        for (int j = lane; j < len; j += 32) {
            int r2 = g_rowlist[start + j];
            const float* kp = &g_K[(size_t)r2 * PDIM + hoff];
            float sdot = 0.f;
#pragma unroll
            for (int e = 0; e < 32; e++) sdot = fmaf(qv[e], kp[e], sdot);
            float w = __expf(sdot * scale - m);
            l += w;
            const float* vp = &g_V[(size_t)r2 * PDIM + hoff];
#pragma unroll
            for (int e = 0; e < 32; e++) accv[e] = fmaf(w, vp[e], accv[e]);
        }
#pragma unroll
        for (int o = 16; o > 0; o >>= 1) l += __shfl_xor_sync(0xffffffffu, l, o);
#pragma unroll
        for (int e = 0; e < 32; e++) {
            float r = accv[e];
#pragma unroll
            for (int o = 16; o > 0; o >>= 1) r += __shfl_xor_sync(0xffffffffu, r, o);
            if (lane == 0) qbuf[warp][e] = r;
        }
        __syncwarp();
        out[(size_t)row * PDIM + hoff + lane] = qbuf[warp][lane] / l;
        __syncwarp();
    }
}

// ---------------------------------------------------------------------------
extern "C" void kernel_launch(void* const* d_in, const int* in_sizes, int n_in,
                              void* d_out, int out_size)
{
    const float* inp = (const float*)d_in[0];
    const int*   pos = (const int*)d_in[1];
    const float* Wq  = (const float*)d_in[2];
    const float* bq  = (const float*)d_in[3];
    const float* Wk  = (const float*)d_in[4];
    const float* bk  = (const float*)d_in[5];
    const float* Wv  = (const float*)d_in[6];
    const float* bv  = (const float*)d_in[7];
    float* out = (float*)d_out;
    const int n = in_sizes[1];

    cudaFuncSetAttribute(qkv_build, cudaFuncAttributeMaxDynamicSharedMemorySize, QKV_SMEM_BYTES);
    cudaFuncSetAttribute(seg_attn, cudaFuncAttributeMaxDynamicSharedMemorySize, ATTN_SMEM_BYTES);

    const int row_blocks = (n + 63) / 64;
    qkv_build<<<dim3(row_blocks, 4), 256, QKV_SMEM_BYTES>>>(inp, Wq, bq, Wk, bk, Wv, bv, pos, n);
    seg_attn<<<dim3(NSEG, HEADS), 1024, ATTN_SMEM_BYTES>>>(out);
    seg_attn_slow<<<dim3(NSEG, HEADS), 512>>>(out);
}

// round 10
// speedup vs baseline: 1.7633x; 1.0499x over previous
#include <cuda_runtime.h>
#include <cstdint>

#define PDIM 128
#define HEADS 4
#define EDIM 32
#define NSEG 32
#define CAP 192
#define NMAX 4096
#define QST_PITCH 196
#define KPITCH 36
#define NK_MAX 6

// Scratch (allocation-free rule: device globals)
__device__ float g_Q[NMAX * PDIM];
__device__ float g_K[NMAX * PDIM];
__device__ float g_V[NMAX * PDIM];
__device__ int   g_rowlist[NMAX];
__device__ int   g_segstart[NSEG + 1];

// ---- GEMM smem (u32 units). bf16-pair words [row][kpair], pitch 68.
#define SPITCH 68
#define AS_H 0
#define AS_L (AS_H + 64 * SPITCH)
#define BS_H (AS_L + 64 * SPITCH)
#define BS_L (BS_H + 64 * SPITCH)
#define QKV_SMEM_BYTES ((BS_L + 64 * SPITCH) * 4)

// attn smem: Ks[192][36] + Vs[192][32] + QsT[32][196] + wb[32][32][4] + rows[192]
#define ATTN_SMEM_BYTES ((CAP*KPITCH + CAP*32 + 32*QST_PITCH + 32*32*4) * 4 + CAP * 4)

// bf16 m16n8k16 MMA, fp32 accumulate (sm_80+ PTX; works on plain sm_103 target)
#define MMA_BF16(d, a0, a1, a2, a3, b0, b1) \
    asm volatile("mma.sync.aligned.m16n8k16.row.col.f32.bf16.bf16.f32 " \
        "{%0,%1,%2,%3}, {%4,%5,%6,%7}, {%8,%9}, {%0,%1,%2,%3};" \
        : "+f"((d)[0]), "+f"((d)[1]), "+f"((d)[2]), "+f"((d)[3]) \
        : "r"(a0), "r"(a1), "r"(a2), "r"(a3), "r"(b0), "r"(b1))

__device__ __forceinline__ void split_pack(float x, float y, uint32_t& hi, uint32_t& lo) {
    uint32_t ux = __float_as_uint(x), uy = __float_as_uint(y);
    hi = __byte_perm(ux, uy, 0x7632);
    float hx = __uint_as_float(ux & 0xFFFF0000u);
    float hy = __uint_as_float(uy & 0xFFFF0000u);
    lo = __byte_perm(__float_as_uint(x - hx), __float_as_uint(y - hy), 0x7632);
}

// ---------------------------------------------------------------------------
// Kernel 1 (fused): bf16-split tensor-core QKV projection + segment build.
// grid (n/64, 7), block 256, 3 CTAs/SM.
//  y<6: 64x64x128 GEMM tile. which = y>>1, n-half = y&1. Warp tile 32x16.
//  y==6, x==0: deterministic stable counting sort of rows by segment.
// ---------------------------------------------------------------------------
__global__ __launch_bounds__(256, 3)
void qkv_build(const float* __restrict__ inp,
               const float* __restrict__ Wq, const float* __restrict__ bq,
               const float* __restrict__ Wk, const float* __restrict__ bk,
               const float* __restrict__ Wv, const float* __restrict__ bv,
               const int* __restrict__ pos, int n)
{
    extern __shared__ float sm[];
    const int y = blockIdx.y;
    const int tid = threadIdx.x;

    if (y == 6) {
        // ---------------- build_seg path ----------------
        if (blockIdx.x != 0) return;
        int* cnt  = (int*)sm;            // [NSEG*256]
        int* tsum = cnt + NSEG * 256;    // [256]

        const int t = tid;
        const int chunk = (n + 255) / 256;
        const int lo = t * chunk;
        const int hi = min(n, lo + chunk);

#pragma unroll
        for (int s = 0; s < NSEG; s++) cnt[s * 256 + t] = 0;
        __syncthreads();
        for (int i = lo; i < hi; i++) cnt[pos[i] * 256 + t]++;
        __syncthreads();
        {
            int sum = 0;
#pragma unroll
            for (int j = 0; j < 32; j++) {
                int v = cnt[t * 32 + j];
                cnt[t * 32 + j] = sum;
                sum += v;
            }
            tsum[t] = sum;
        }
        __syncthreads();
        if (t == 0) {
            int a = 0;
            for (int i = 0; i < 256; i++) { int v = tsum[i]; tsum[i] = a; a += v; }
        }
        __syncthreads();
        {
            int b = tsum[t];
#pragma unroll
            for (int j = 0; j < 32; j++) cnt[t * 32 + j] += b;
        }
        __syncthreads();
        if (t < NSEG) g_segstart[t] = cnt[t * 256 + 0];
        if (t == 0) g_segstart[NSEG] = n;
        for (int i = lo; i < hi; i++) {
            int s = pos[i];
            int idx = cnt[s * 256 + t]++;
            g_rowlist[idx] = i;
        }
        return;
    }

    // ---------------- tensor GEMM path ----------------
    const int which = y >> 1;
    const int nhalf = y & 1;
    const float* W    = (which == 0) ? Wq : (which == 1) ? Wk : Wv;
    const float* bias = (which == 0) ? bq : (which == 1) ? bk : bv;
    float* Out        = (which == 0) ? g_Q : (which == 1) ? g_K : g_V;

    uint32_t* smu = (uint32_t*)sm;
    const int base = blockIdx.x * 64;

    // Stage A (64 rows x 64 kpairs): coalesced float2 LDG, conflict-free STS
    for (int i = tid; i < 64 * 64; i += 256) {
        int r = i >> 6, kp = i & 63;
        int row = min(base + r, n - 1);
        float2 a = *(const float2*)&inp[(size_t)row * PDIM + kp * 2];
        uint32_t h, l;
        split_pack(a.x, a.y, h, l);
        smu[AS_H + r * SPITCH + kp] = h;
        smu[AS_L + r * SPITCH + kp] = l;
    }
    // Stage B (64 local cols x 64 kpairs): coalesced LDG over nn, XOR-swizzled STS
    for (int i = tid; i < 64 * 64; i += 256) {
        int nnl = i & 63, kp = i >> 6;
        int nn = nhalf * 64 + nnl;
        float w0 = W[(2 * kp) * PDIM + nn];
        float w1 = W[(2 * kp + 1) * PDIM + nn];
        uint32_t h, l;
        split_pack(w0, w1, h, l);
        int kps = kp ^ ((nnl >> 3) & 3);
        smu[BS_H + nnl * SPITCH + kps] = h;
        smu[BS_L + nnl * SPITCH + kps] = l;
    }
    __syncthreads();

    const int lane = tid & 31, wid = tid >> 5;
    const int wtm = wid >> 2, wtn = wid & 3;     // 2 warps in M (32 rows), 4 in N (16 cols)
    const int l4 = lane >> 2, lq = lane & 3;

    float acc[2][2][4];
#pragma unroll
    for (int mt = 0; mt < 2; mt++)
#pragma unroll
        for (int nt = 0; nt < 2; nt++)
#pragma unroll
            for (int c = 0; c < 4; c++) acc[mt][nt][c] = 0.f;

#pragma unroll
    for (int ks = 0; ks < 8; ks++) {
        const int kb = ks * 8 + lq;
        uint32_t ah[2][4], al[2][4];
#pragma unroll
        for (int mt = 0; mt < 2; mt++) {
            int r = wtm * 32 + mt * 16 + l4;
            ah[mt][0] = smu[AS_H + r * SPITCH + kb];
            ah[mt][1] = smu[AS_H + (r + 8) * SPITCH + kb];
            ah[mt][2] = smu[AS_H + r * SPITCH + kb + 4];
            ah[mt][3] = smu[AS_H + (r + 8) * SPITCH + kb + 4];
            al[mt][0] = smu[AS_L + r * SPITCH + kb];
            al[mt][1] = smu[AS_L + (r + 8) * SPITCH + kb];
            al[mt][2] = smu[AS_L + r * SPITCH + kb + 4];
            al[mt][3] = smu[AS_L + (r + 8) * SPITCH + kb + 4];
        }
#pragma unroll
        for (int nt = 0; nt < 2; nt++) {
            int c = wtn * 16 + nt * 8 + l4;
            int kbs = kb ^ ((wtn * 2 + nt) & 3);
            uint32_t bh0 = smu[BS_H + c * SPITCH + kbs];
            uint32_t bh1 = smu[BS_H + c * SPITCH + kbs + 4];
            uint32_t bl0 = smu[BS_L + c * SPITCH + kbs];
            uint32_t bl1 = smu[BS_L + c * SPITCH + kbs + 4];
#pragma unroll
            for (int mt = 0; mt < 2; mt++) {
                MMA_BF16(acc[mt][nt], ah[mt][0], ah[mt][1], ah[mt][2], ah[mt][3], bh0, bh1);
                MMA_BF16(acc[mt][nt], al[mt][0], al[mt][1], al[mt][2], al[mt][3], bh0, bh1);
                MMA_BF16(acc[mt][nt], ah[mt][0], ah[mt][1], ah[mt][2], ah[mt][3], bl0, bl1);
            }
        }
    }

    // Epilogue
#pragma unroll
    for (int nt = 0; nt < 2; nt++) {
        int col = nhalf * 64 + wtn * 16 + nt * 8 + lq * 2;
        float2 bi = *(const float2*)&bias[col];
#pragma unroll
        for (int mt = 0; mt < 2; mt++) {
            int row0 = base + wtm * 32 + mt * 16 + l4;
            if (row0 < n) {
                float2 o; o.x = acc[mt][nt][0] + bi.x; o.y = acc[mt][nt][1] + bi.y;
                *(float2*)&Out[(size_t)row0 * PDIM + col] = o;
            }
            if (row0 + 8 < n) {
                float2 o; o.x = acc[mt][nt][2] + bi.x; o.y = acc[mt][nt][3] + bi.y;
                *(float2*)&Out[(size_t)(row0 + 8) * PDIM + col] = o;
            }
        }
    }
}

// ---------------------------------------------------------------------------
// Kernel 2: fast-path attention. grid (NSEG, HEADS), block 1024 (32 warps).
// 4 queries/warp; K rows read as batched float4 halves.
// ---------------------------------------------------------------------------
__global__ __launch_bounds__(1024)
void seg_attn(float* __restrict__ out)
{
    extern __shared__ float sm[];
    float* Ks  = sm;                          // [CAP][36]
    float* Vs  = Ks + CAP * KPITCH;           // [CAP][32]
    float* QsT = Vs + CAP * 32;               // [32][196]
    float* wb  = QsT + 32 * QST_PITCH;        // [32 warps][32][4]
    int*  rows = (int*)(wb + 32 * 32 * 4);    // [CAP]

    const int s = blockIdx.x, h = blockIdx.y;
    const int start = g_segstart[s];
    const int len = g_segstart[s + 1] - start;
    if (len == 0 || len > CAP) return;

    const int tid = threadIdx.x, lane = tid & 31, warp = tid >> 5;
    const int hoff = h * EDIM;
    const float scale = 0.17677669529663687f;   // 1/sqrt(32)

    const int nk = (len + 31) >> 5;
    const int lenp = nk * 32;

    if (tid < len) rows[tid] = g_rowlist[start + tid];
    for (int i = tid; i < lenp * 8; i += 1024) {
        int j = i >> 3, e4 = i & 7;
        float4 kv = make_float4(0.f, 0.f, 0.f, 0.f);
        float4 vv = kv, qv = kv;
        if (j < len) {
            int row = g_rowlist[start + j];
            kv = *(const float4*)&g_K[(size_t)row * PDIM + hoff + e4 * 4];
            vv = *(const float4*)&g_V[(size_t)row * PDIM + hoff + e4 * 4];
            qv = *(const float4*)&g_Q[(size_t)row * PDIM + hoff + e4 * 4];
        }
        *(float4*)&Ks[j * KPITCH + e4 * 4] = kv;
        *(float4*)&Vs[j * 32 + e4 * 4] = vv;
        QsT[(e4 * 4 + 0) * QST_PITCH + j] = qv.x;
        QsT[(e4 * 4 + 1) * QST_PITCH + j] = qv.y;
        QsT[(e4 * 4 + 2) * QST_PITCH + j] = qv.z;
        QsT[(e4 * 4 + 3) * QST_PITCH + j] = qv.w;
    }
    __syncthreads();

    float* wbW = wb + warp * 128;

    for (int qb = warp * 4; qb < len; qb += 128) {
        // ---- scores: lane = key within chunk, K in register halves ----
        float sc[4][NK_MAX];
#pragma unroll
        for (int kk = 0; kk < NK_MAX; kk++) {
            if (kk < nk) {
                int j = kk * 32 + lane;
                float a0 = 0.f, a1 = 0.f, a2 = 0.f, a3 = 0.f;
                const float* kp = &Ks[j * KPITCH];
#pragma unroll
                for (int half = 0; half < 2; half++) {
                    float4 kr[4];
#pragma unroll
                    for (int c = 0; c < 4; c++)
                        kr[c] = *(const float4*)&kp[half * 16 + c * 4];
#pragma unroll
                    for (int ee = 0; ee < 16; ee++) {
                        int e = half * 16 + ee;
                        float ke = ((const float*)kr)[ee];
                        float4 q4 = *(const float4*)&QsT[e * QST_PITCH + qb];
                        a0 = fmaf(ke, q4.x, a0);
                        a1 = fmaf(ke, q4.y, a1);
                        a2 = fmaf(ke, q4.z, a2);
                        a3 = fmaf(ke, q4.w, a3);
                    }
                }
                bool valid = (j < len);
                sc[0][kk] = valid ? a0 * scale : -1e30f;
                sc[1][kk] = valid ? a1 * scale : -1e30f;
                sc[2][kk] = valid ? a2 * scale : -1e30f;
                sc[3][kk] = valid ? a3 * scale : -1e30f;
            }
        }
        // ---- softmax per query ----
        float inv[4];
#pragma unroll
        for (int qi = 0; qi < 4; qi++) {
            float m = -1e30f;
#pragma unroll
            for (int kk = 0; kk < NK_MAX; kk++)
                if (kk < nk) m = fmaxf(m, sc[qi][kk]);
#pragma unroll
            for (int o = 16; o > 0; o >>= 1)
                m = fmaxf(m, __shfl_xor_sync(0xffffffffu, m, o));
            float l = 0.f;
#pragma unroll
            for (int kk = 0; kk < NK_MAX; kk++) {
                if (kk < nk) {
                    float e = __expf(sc[qi][kk] - m);
                    sc[qi][kk] = e;
                    l += e;
                }
            }
#pragma unroll
            for (int o = 16; o > 0; o >>= 1)
                l += __shfl_xor_sync(0xffffffffu, l, o);
            inv[qi] = 1.f / l;
        }
        // ---- PV through per-warp staging ----
        float a0 = 0.f, a1 = 0.f, a2 = 0.f, a3 = 0.f;
#pragma unroll
        for (int kk = 0; kk < NK_MAX; kk++) {
            if (kk < nk) {
                float4 w4;
                w4.x = sc[0][kk] * inv[0];
                w4.y = sc[1][kk] * inv[1];
                w4.z = sc[2][kk] * inv[2];
                w4.w = sc[3][kk] * inv[3];
                *(float4*)&wbW[lane * 4] = w4;
                __syncwarp();
                const float* vbase = &Vs[kk * 32 * 32 + lane];
#pragma unroll
                for (int src = 0; src < 32; src++) {
                    float v = vbase[src * 32];
                    float4 w = *(const float4*)&wbW[src * 4];
                    a0 = fmaf(w.x, v, a0); a1 = fmaf(w.y, v, a1);
                    a2 = fmaf(w.z, v, a2); a3 = fmaf(w.w, v, a3);
                }
                __syncwarp();
            }
        }

        if (qb + 0 < len) out[(size_t)rows[qb + 0] * PDIM + hoff + lane] = a0;
        if (qb + 1 < len) out[(size_t)rows[qb + 1] * PDIM + hoff + lane] = a1;
        if (qb + 2 < len) out[(size_t)rows[qb + 2] * PDIM + hoff + lane] = a2;
        if (qb + 3 < len) out[(size_t)rows[qb + 3] * PDIM + hoff + lane] = a3;
    }
}

// ---------------------------------------------------------------------------
// Kernel 3: slow-path attention for len > CAP (statistically never; early-exit).
// ---------------------------------------------------------------------------
__global__ __launch_bounds__(512)
void seg_attn_slow(float* __restrict__ out)
{
    const int s = blockIdx.x, h = blockIdx.y;
    const int start = g_segstart[s];
    const int len = g_segstart[s + 1] - start;
    if (len <= CAP) return;

    __shared__ float qbuf[16][32];
    const int tid = threadIdx.x, lane = tid & 31, warp = tid >> 5;
    const int hoff = h * EDIM;
    const float scale = 0.17677669529663687f;

    for (int q = warp; q < len; q += 16) {
        const int row = g_rowlist[start + q];
        qbuf[warp][lane] = g_Q[(size_t)row * PDIM + hoff + lane];
        __syncwarp();
        float qv[32];
#pragma unroll
        for (int e = 0; e < 32; e++) qv[e] = qbuf[warp][e];

        float m = -1e30f;
        for (int j = lane; j < len; j += 32) {
            const float* kp = &g_K[(size_t)g_rowlist[start + j] * PDIM + hoff];
            float sdot = 0.f;
#pragma unroll
            for (int e = 0; e < 32; e++) sdot = fmaf(qv[e], kp[e], sdot);
            m = fmaxf(m, sdot * scale);
        }
#pragma unroll
        for (int o = 16; o > 0; o >>= 1) m = fmaxf(m, __shfl_xor_sync(0xffffffffu, m, o));

        float l = 0.f;
        float accv[32];
#pragma unroll
        for (int e = 0; e < 32; e++) accv[e] = 0.f;
        for (int j = lane; j < len; j += 32) {
            int r2 = g_rowlist[start + j];
            const float* kp = &g_K[(size_t)r2 * PDIM + hoff];
            float sdot = 0.f;
#pragma unroll
            for (int e = 0; e < 32; e++) sdot = fmaf(qv[e], kp[e], sdot);
            float w = __expf(sdot * scale - m);
            l += w;
            const float* vp = &g_V[(size_t)r2 * PDIM + hoff];
#pragma unroll
            for (int e = 0; e < 32; e++) accv[e] = fmaf(w, vp[e], accv[e]);
        }
#pragma unroll
        for (int o = 16; o > 0; o >>= 1) l += __shfl_xor_sync(0xffffffffu, l, o);
#pragma unroll
        for (int e = 0; e < 32; e++) {
            float r = accv[e];
#pragma unroll
            for (int o = 16; o > 0; o >>= 1) r += __shfl_xor_sync(0xffffffffu, r, o);
            if (lane == 0) qbuf[warp][e] = r;
        }
        __syncwarp();
        out[(size_t)row * PDIM + hoff + lane] = qbuf[warp][lane] / l;
        __syncwarp();
    }
}

// ---------------------------------------------------------------------------
extern "C" void kernel_launch(void* const* d_in, const int* in_sizes, int n_in,
                              void* d_out, int out_size)
{
    const float* inp = (const float*)d_in[0];
    const int*   pos = (const int*)d_in[1];
    const float* Wq  = (const float*)d_in[2];
    const float* bq  = (const float*)d_in[3];
    const float* Wk  = (const float*)d_in[4];
    const float* bk  = (const float*)d_in[5];
    const float* Wv  = (const float*)d_in[6];
    const float* bv  = (const float*)d_in[7];
    float* out = (float*)d_out;
    const int n = in_sizes[1];

    cudaFuncSetAttribute(qkv_build, cudaFuncAttributeMaxDynamicSharedMemorySize, QKV_SMEM_BYTES);
    cudaFuncSetAttribute(seg_attn, cudaFuncAttributeMaxDynamicSharedMemorySize, ATTN_SMEM_BYTES);

    const int row_blocks = (n + 63) / 64;
    qkv_build<<<dim3(row_blocks, 7), 256, QKV_SMEM_BYTES>>>(inp, Wq, bq, Wk, bk, Wv, bv, pos, n);
    seg_attn<<<dim3(NSEG, HEADS), 1024, ATTN_SMEM_BYTES>>>(out);
    seg_attn_slow<<<dim3(NSEG, HEADS), 512>>>(out);
}